// round 12
// baseline (speedup 1.0000x reference)
#include <cuda_runtime.h>
#include <cstdint>

#define TT 2048
#define BB 128
#define HH 256
#define II 64
#define NCTA 128
#define NTH 512
#define K0 (II + HH)
#define K1 (HH + HH)
#define LDW0 (K0 + 4)
#define LDW1 (K1 + 4)
#define RED_OFF (64 * LDW1 + 64)
#define SMEMB ((RED_OFF + 3 * 2048) * 4)

// A operands stored TRANSPOSED [k][batch] as pre-split (hi,lo) float2
__device__ float2 g_x2[(size_t)TT * II * BB];
__device__ float2 g_h0[2][HH * BB];
__device__ float2 g_h1[2][HH * BB];
__device__ unsigned g_cnt;
__device__ unsigned g_gen;

__device__ __forceinline__ void gbar() {
    __syncthreads();
    if (threadIdx.x == 0) {
        unsigned old = *((volatile unsigned*)&g_gen);
        __threadfence();
        if (atomicAdd(&g_cnt, 1u) == NCTA - 1) {
            atomicExch(&g_cnt, 0u);
            __threadfence();
            atomicAdd(&g_gen, 1u);
        } else {
            while (*((volatile unsigned*)&g_gen) == old) { }
        }
        __threadfence();
    }
    __syncthreads();
}

__device__ __forceinline__ void split(float x, unsigned& hi, unsigned& lo) {
    asm("cvt.rna.tf32.f32 %0, %1;" : "=r"(hi) : "f"(x));
    float r = x - __uint_as_float(hi);
    asm("cvt.rna.tf32.f32 %0, %1;" : "=r"(lo) : "f"(r));
}

__device__ __forceinline__ float2 split2(float x) {
    unsigned hi, lo;
    split(x, hi, lo);
    return make_float2(__uint_as_float(hi), __uint_as_float(lo));
}

__device__ __forceinline__ void mma8(float (&c)[4], float a0, float a1,
                                     float a2, float a3, float b0, float b1) {
    asm volatile(
        "mma.sync.aligned.m16n8k8.row.col.f32.tf32.tf32.f32 "
        "{%0,%1,%2,%3},{%4,%5,%6,%7},{%8,%9},{%0,%1,%2,%3};"
        : "+f"(c[0]), "+f"(c[1]), "+f"(c[2]), "+f"(c[3])
        : "r"(__float_as_uint(a0)), "r"(__float_as_uint(a1)),
          "r"(__float_as_uint(a2)), "r"(__float_as_uint(a3)),
          "r"(__float_as_uint(b0)), "r"(__float_as_uint(b1)));
}

__device__ __forceinline__ float sigm(float x) { return 1.0f / (1.0f + __expf(-x)); }
__device__ __forceinline__ float tanhx(float x) { return 1.0f - 2.0f / (__expf(2.0f * x) + 1.0f); }

// A: k-major [nk][BB] float2 (hi,lo). koff = global k offset into weights.
// mma terms interleaved across gates so same-acc mmas are 4 issues apart.
__device__ __forceinline__ void gemm_span(float (&acc)[4][4],
                                          const float2* __restrict__ A, int nk, int koff,
                                          const float* __restrict__ WHi,
                                          const float* __restrict__ WLo,
                                          int ldw, int r0, int lane) {
    const int kk = lane & 3;
    const int gq = lane >> 2;
    const float2* p = A + kk * BB + r0;
    const float* wh = WHi + gq * ldw + koff + 2 * kk;
    const float* wo = WLo + gq * ldw + koff + 2 * kk;
#pragma unroll 4
    for (int k = 0; k < nk; k += 8) {
        float2 e0 = __ldcg(p + k * BB);
        float2 e1 = __ldcg(p + k * BB + 8);
        float2 e2 = __ldcg(p + (k + 4) * BB);
        float2 e3 = __ldcg(p + (k + 4) * BB + 8);
        float2 bh[4], bl[4];
#pragma unroll
        for (int g = 0; g < 4; ++g) {
            bh[g] = *reinterpret_cast<const float2*>(wh + g * 8 * ldw + k);
            bl[g] = *reinterpret_cast<const float2*>(wo + g * 8 * ldw + k);
        }
#pragma unroll
        for (int g = 0; g < 4; ++g)
            mma8(acc[g], e0.x, e1.x, e2.x, e3.x, bh[g].x, bh[g].y);
#pragma unroll
        for (int g = 0; g < 4; ++g)
            mma8(acc[g], e0.y, e1.y, e2.y, e3.y, bh[g].x, bh[g].y);
#pragma unroll
        for (int g = 0; g < 4; ++g)
            mma8(acc[g], e0.x, e1.x, e2.x, e3.x, bl[g].x, bl[g].y);
    }
}

__global__ void __launch_bounds__(NTH, 1)
lstm_kernel(const float* __restrict__ x, const float* __restrict__ h0in,
            const float* __restrict__ c0in,
            const float* __restrict__ Wih0, const float* __restrict__ Whh0,
            const float* __restrict__ bih0, const float* __restrict__ bhh0,
            const float* __restrict__ Wih1, const float* __restrict__ Whh1,
            const float* __restrict__ bih1, const float* __restrict__ bhh1,
            const float* __restrict__ Wlin, const float* __restrict__ blin,
            float* __restrict__ out) {
    extern __shared__ float sh[];
    const int tid = threadIdx.x;
    const int cta = blockIdx.x;
    const int layer = cta >> 6;
    const int sub = cta & 63;
    const int cb = (sub >> 1) * 8;     // first hidden column (8 per CTA)
    const int bhalf = sub & 1;
    const int K = layer ? K1 : K0;
    const int ldw = layer ? LDW1 : LDW0;
    const int KX = layer ? HH : II;
    const float* Wih = layer ? Wih1 : Wih0;
    const float* Whh = layer ? Whh1 : Whh0;
    const float* bi = layer ? bih1 : bih0;
    const float* bh = layer ? bhh1 : bhh0;

    float* WHi = sh;
    float* WLo = sh + 32 * ldw;
    float* bs = sh + 64 * ldw;
    float* wl = bs + 32;
    float4* red = (float4*)(sh + RED_OFF);   // [3][4 gates][128]

    // init: transpose+split x and h0 into k-major scratch; out = b_lin
    {
        int g = cta * NTH + tid, gs = NCTA * NTH;
        for (size_t i = g; i < (size_t)TT * BB * II; i += gs) {
            size_t t = i / (BB * II);
            int rem = (int)(i - t * (BB * II));
            int r = rem / II, k = rem - r * II;
            g_x2[t * (II * BB) + k * BB + r] = split2(x[i]);
        }
        for (int i = g; i < BB * HH; i += gs) {
            int r = i / HH, k = i - r * HH;
            g_h0[1][k * BB + r] = split2(h0in[i]);
            g_h1[1][k * BB + r] = split2(h0in[BB * HH + i]);
        }
        float bl = blin[0];
        for (int i = g; i < TT * BB; i += gs) out[i] = bl;
    }

    // stage split weights (pair-interleaved within each 8-wide k-group)
    for (int i = tid; i < 32 * K; i += NTH) {
        int n = i / K, k = i - n * K;
        int row = (n >> 3) * HH + cb + (n & 7);
        float wv = (k < KX) ? Wih[row * KX + k] : Whh[row * HH + (k - KX)];
        unsigned hi, lo;
        split(wv, hi, lo);
        int ko = n * ldw + (k & ~7) + 2 * (k & 3) + ((k >> 2) & 1);
        WHi[ko] = __uint_as_float(hi);
        WLo[ko] = __uint_as_float(lo);
    }
    if (tid < 32) {
        int row = (tid >> 3) * HH + cb + (tid & 7);
        bs[tid] = bi[row] + bh[row];
    }
    if (tid < 8) wl[tid] = layer ? Wlin[cb + tid] : 0.0f;
    __syncthreads();

    const int w = tid >> 5;            // 16 warps
    const int wk = w & 3;              // K-quarter
    const int wr = w >> 2;             // row tile 0..3
    const int lane = tid & 31;
    const int r0 = 64 * bhalf + 16 * wr + (lane >> 2);  // rows r0, r0+8
    const int j0 = 2 * (lane & 3);

    float cs[4] = {0.f, 0.f, 0.f, 0.f};
    if (wk == 0) {
        const float* c0p = c0in + layer * BB * HH;
        cs[0] = c0p[r0 * HH + cb + j0];
        cs[1] = c0p[r0 * HH + cb + j0 + 1];
        cs[2] = c0p[(r0 + 8) * HH + cb + j0];
        cs[3] = c0p[(r0 + 8) * HH + cb + j0 + 1];
    }

    float bz0[4], bz1[4];
#pragma unroll
    for (int g = 0; g < 4; ++g) {
        bz0[g] = bs[g * 8 + j0];
        bz1[g] = bs[g * 8 + j0 + 1];
    }
    const float wl0 = wl[j0], wl1 = wl[j0 + 1];

    gbar();

#pragma unroll 1
    for (int s = 0; s <= TT; ++s) {
        const bool active = layer ? (s >= 1) : (s < TT);
        float acc[4][4];
        if (active) {
            if (wk == 0) {
#pragma unroll
                for (int g = 0; g < 4; ++g) {
                    acc[g][0] = bz0[g]; acc[g][1] = bz1[g];
                    acc[g][2] = bz0[g]; acc[g][3] = bz1[g];
                }
            } else {
#pragma unroll
                for (int g = 0; g < 4; ++g)
                    acc[g][0] = acc[g][1] = acc[g][2] = acc[g][3] = 0.0f;
            }
            if (layer == 0) {
                // K0=320 split 80/80/80/80: wk0 = x(64) + h[0:16)
                const float2* hprev = g_h0[(s + 1) & 1];
                if (wk == 0) {
                    gemm_span(acc, g_x2 + (size_t)s * (II * BB), II, 0, WHi, WLo, ldw, r0, lane);
                    gemm_span(acc, hprev, 16, II, WHi, WLo, ldw, r0, lane);
                } else {
                    int hk = 16 + (wk - 1) * 80;   // local h k-offset
                    gemm_span(acc, hprev + hk * BB, 80, II + hk, WHi, WLo, ldw, r0, lane);
                }
            } else {
                // K1=512 split 128 each: wk0,1 on h0; wk2,3 on h1
                int t = s - 1;
                if (wk < 2) {
                    gemm_span(acc, g_h0[t & 1] + wk * 128 * BB, 128, wk * 128,
                              WHi, WLo, ldw, r0, lane);
                } else {
                    gemm_span(acc, g_h1[s & 1] + (wk - 2) * 128 * BB, 128,
                              HH + (wk - 2) * 128, WHi, WLo, ldw, r0, lane);
                }
            }
            if (wk != 0) {
#pragma unroll
                for (int g = 0; g < 4; ++g)
                    red[((wk - 1) * 4 + g) * 128 + wr * 32 + lane] =
                        make_float4(acc[g][0], acc[g][1], acc[g][2], acc[g][3]);
            }
        }
        __syncthreads();
        if (active && wk == 0) {
#pragma unroll
            for (int q = 0; q < 3; ++q)
#pragma unroll
                for (int g = 0; g < 4; ++g) {
                    float4 v = red[(q * 4 + g) * 128 + wr * 32 + lane];
                    acc[g][0] += v.x; acc[g][1] += v.y;
                    acc[g][2] += v.z; acc[g][3] += v.w;
                }
            float h[4];
#pragma unroll
            for (int e = 0; e < 4; ++e) {
                float ig = sigm(acc[0][e]);
                float fg = sigm(acc[1][e]);
                float gg = tanhx(acc[2][e]);
                float og = sigm(acc[3][e]);
                float c = fg * cs[e] + ig * gg;
                cs[e] = c;
                h[e] = og * tanhx(c);
            }
            float2* hb2 = layer ? g_h1[(s - 1) & 1] : g_h0[s & 1];
#pragma unroll
            for (int e = 0; e < 4; ++e) {
                int rr = (e & 2) ? (r0 + 8) : r0;
                hb2[(cb + j0 + (e & 1)) * BB + rr] = split2(h[e]);
            }
            if (layer == 1) {
                int t = s - 1;
                float p0 = h[0] * wl0 + h[1] * wl1;
                float p1 = h[2] * wl0 + h[3] * wl1;
                p0 += __shfl_xor_sync(0xffffffffu, p0, 1);
                p0 += __shfl_xor_sync(0xffffffffu, p0, 2);
                p1 += __shfl_xor_sync(0xffffffffu, p1, 1);
                p1 += __shfl_xor_sync(0xffffffffu, p1, 2);
                if ((lane & 3) == 0) {
                    atomicAdd(out + (size_t)t * BB + r0, p0);
                    atomicAdd(out + (size_t)t * BB + r0 + 8, p1);
                }
            }
        }
        gbar();
    }
}

extern "C" void kernel_launch(void* const* d_in, const int* in_sizes, int n_in,
                              void* d_out, int out_size) {
    (void)in_sizes; (void)n_in; (void)out_size;
    cudaFuncSetAttribute(lstm_kernel, cudaFuncAttributeMaxDynamicSharedMemorySize, SMEMB);
    lstm_kernel<<<NCTA, NTH, SMEMB>>>(
        (const float*)d_in[0], (const float*)d_in[1], (const float*)d_in[2],
        (const float*)d_in[3], (const float*)d_in[4], (const float*)d_in[5],
        (const float*)d_in[6], (const float*)d_in[7], (const float*)d_in[8],
        (const float*)d_in[9], (const float*)d_in[10], (const float*)d_in[11],
        (const float*)d_in[12], (float*)d_out);
}

// round 15
// speedup vs baseline: 2.4624x; 2.4624x over previous
#include <cuda_runtime.h>
#include <cuda_bf16.h>
#include <cstdint>

#define TT 2048
#define BB 128
#define HH 256
#define II 64
#define NCTA 128
#define NTH 256
#define K0 (II + HH)      // 320
#define K1 (HH + HH)      // 512
#define P0 (K0 / 2)       // 160 pairs
#define P1 (K1 / 2)       // 256 pairs
#define LDP0 (P0 + 8)     // 168
#define LDP1 (P1 + 8)     // 264
#define WSH_WORDS (32 * LDP1)
#define BS_OFF (WSH_WORDS * 8)
#define WL_OFF (BS_OFF + 32 * 4)
#define RED_OFF (WL_OFF + 64)
#define SMEMB (RED_OFF + 512 * 16)

// A operands: [pair][batch] uint2 = (bf16x2 hi-plane pair, bf16x2 lo-plane pair)
__device__ uint2 g_x2[(size_t)TT * (II / 2) * BB];
__device__ uint2 g_h0[2][(HH / 2) * BB];
__device__ uint2 g_h1[2][(HH / 2) * BB];
__device__ unsigned g_cnt;
__device__ unsigned g_gen;

__device__ __forceinline__ void gbar() {
    __syncthreads();
    if (threadIdx.x == 0) {
        unsigned old = *((volatile unsigned*)&g_gen);
        __threadfence();
        if (atomicAdd(&g_cnt, 1u) == NCTA - 1) {
            atomicExch(&g_cnt, 0u);
            __threadfence();
            atomicAdd(&g_gen, 1u);
        } else {
            while (*((volatile unsigned*)&g_gen) == old) { }
        }
        __threadfence();
    }
    __syncthreads();
}

// split a,b into bf16 hi/lo planes; word layout: low 16 bits = first element
__device__ __forceinline__ uint2 split_pair(float a, float b) {
    __nv_bfloat16 ah = __float2bfloat16(a);
    __nv_bfloat16 bh = __float2bfloat16(b);
    __nv_bfloat16 al = __float2bfloat16(a - __bfloat162float(ah));
    __nv_bfloat16 bl = __float2bfloat16(b - __bfloat162float(bh));
    unsigned hw = ((unsigned)__bfloat16_as_ushort(bh) << 16) | __bfloat16_as_ushort(ah);
    unsigned lw = ((unsigned)__bfloat16_as_ushort(bl) << 16) | __bfloat16_as_ushort(al);
    return make_uint2(hw, lw);
}

__device__ __forceinline__ void mma16(float (&c)[4], unsigned a0, unsigned a1,
                                      unsigned a2, unsigned a3, unsigned b0, unsigned b1) {
    asm volatile(
        "mma.sync.aligned.m16n8k16.row.col.f32.bf16.bf16.f32 "
        "{%0,%1,%2,%3},{%4,%5,%6,%7},{%8,%9},{%0,%1,%2,%3};"
        : "+f"(c[0]), "+f"(c[1]), "+f"(c[2]), "+f"(c[3])
        : "r"(a0), "r"(a1), "r"(a2), "r"(a3), "r"(b0), "r"(b1));
}

__device__ __forceinline__ float sigm(float x) { return 1.0f / (1.0f + __expf(-x)); }
__device__ __forceinline__ float tanhx(float x) { return 1.0f - 2.0f / (__expf(2.0f * x) + 1.0f); }

// A2: [npairs][BB] uint2 (hi pair word, lo pair word), local pair 0 at A2.
// poff = global pair offset into weights. Wsh words slot-interleaved so the
// uint4 at slot 2*kk yields (hi_kk, lo_kk, hi_{kk+4}, lo_{kk+4}).
__device__ __forceinline__ void gemm_span(float (&acc)[4][4],
                                          const uint2* __restrict__ A2, int npairs, int poff,
                                          const uint2* __restrict__ Wsh, int ldp,
                                          int r0, int lane) {
    const int kk = lane & 3;
    const int gq = lane >> 2;
    const uint2* pA = A2 + kk * BB + r0;
    const uint2* wb = Wsh + gq * ldp + poff + 2 * kk;
#pragma unroll 4
    for (int p = 0; p < npairs; p += 8) {
        uint2 u0 = __ldcg(pA + p * BB);
        uint2 u1 = __ldcg(pA + p * BB + 8);
        uint2 u2 = __ldcg(pA + (p + 4) * BB);
        uint2 u3 = __ldcg(pA + (p + 4) * BB + 8);
        uint4 w4[4];
#pragma unroll
        for (int g = 0; g < 4; ++g)
            w4[g] = *reinterpret_cast<const uint4*>(wb + g * 8 * ldp + p);
#pragma unroll
        for (int g = 0; g < 4; ++g)   // hi*hi
            mma16(acc[g], u0.x, u1.x, u2.x, u3.x, w4[g].x, w4[g].z);
#pragma unroll
        for (int g = 0; g < 4; ++g)   // lo*hi
            mma16(acc[g], u0.y, u1.y, u2.y, u3.y, w4[g].x, w4[g].z);
#pragma unroll
        for (int g = 0; g < 4; ++g)   // hi*lo
            mma16(acc[g], u0.x, u1.x, u2.x, u3.x, w4[g].y, w4[g].w);
    }
}

__global__ void __launch_bounds__(NTH, 1)
lstm_kernel(const float* __restrict__ x, const float* __restrict__ h0in,
            const float* __restrict__ c0in,
            const float* __restrict__ Wih0, const float* __restrict__ Whh0,
            const float* __restrict__ bih0, const float* __restrict__ bhh0,
            const float* __restrict__ Wih1, const float* __restrict__ Whh1,
            const float* __restrict__ bih1, const float* __restrict__ bhh1,
            const float* __restrict__ Wlin, const float* __restrict__ blin,
            float* __restrict__ out) {
    extern __shared__ char sh[];
    uint2* Wsh = (uint2*)sh;
    float* bs = (float*)(sh + BS_OFF);
    float* wl = (float*)(sh + WL_OFF);
    float4* red = (float4*)(sh + RED_OFF);

    const int tid = threadIdx.x;
    const int cta = blockIdx.x;
    const int layer = cta >> 6;
    const int sub = cta & 63;
    const int cb = (sub >> 1) * 8;     // first hidden column (8 per CTA)
    const int bhalf = sub & 1;
    const int P = layer ? P1 : P0;
    const int ldp = layer ? LDP1 : LDP0;
    const int KX = layer ? HH : II;
    const float* Wih = layer ? Wih1 : Wih0;
    const float* Whh = layer ? Whh1 : Whh0;
    const float* bi = layer ? bih1 : bih0;
    const float* bh = layer ? bhh1 : bhh0;

    // init: transpose+split x and initial h into packed bf16 planes; out = b_lin
    {
        int g = cta * NTH + tid, gs = NCTA * NTH;
        for (size_t i = g; i < (size_t)TT * BB * (II / 2); i += gs) {
            size_t t = i / (BB * (II / 2));
            int rem = (int)(i - t * (BB * (II / 2)));
            int r = rem / (II / 2), p = rem - r * (II / 2);
            const float* xp = x + t * (BB * II) + r * II + 2 * p;
            g_x2[t * ((II / 2) * BB) + p * BB + r] = split_pair(xp[0], xp[1]);
        }
        for (int i = g; i < BB * (HH / 2); i += gs) {
            int r = i / (HH / 2), p = i - r * (HH / 2);
            g_h0[1][p * BB + r] = split_pair(h0in[r * HH + 2 * p], h0in[r * HH + 2 * p + 1]);
            const float* hp = h0in + BB * HH + r * HH + 2 * p;
            g_h1[1][p * BB + r] = split_pair(hp[0], hp[1]);
        }
        float bl = blin[0];
        for (int i = g; i < TT * BB; i += gs) out[i] = bl;
    }

    // stage split weights: slot interleave (pair pp<4 -> slot 2pp; else 2(pp-4)+1)
    for (int i = tid; i < 32 * P; i += NTH) {
        int n = i / P, p = i - n * P;
        int row = (n >> 3) * HH + cb + (n & 7);
        int k0 = 2 * p, k1 = 2 * p + 1;
        float w0 = (k0 < KX) ? Wih[row * KX + k0] : Whh[row * HH + (k0 - KX)];
        float w1 = (k1 < KX) ? Wih[row * KX + k1] : Whh[row * HH + (k1 - KX)];
        int kc = p >> 3, pp = p & 7;
        int slot = kc * 8 + ((pp < 4) ? (2 * pp) : (2 * (pp - 4) + 1));
        Wsh[n * ldp + slot] = split_pair(w0, w1);
    }
    if (tid < 32) {
        int row = (tid >> 3) * HH + cb + (tid & 7);
        bs[tid] = bi[row] + bh[row];
    }
    if (tid < 8) wl[tid] = layer ? Wlin[cb + tid] : 0.0f;
    __syncthreads();

    const int w = tid >> 5;            // 8 warps
    const int wk = w & 1;              // K-half
    const int wr = w >> 1;             // row tile 0..3
    const int lane = tid & 31;
    const int r0 = 64 * bhalf + 16 * wr + (lane >> 2);  // rows r0, r0+8
    const int j0 = 2 * (lane & 3);

    float cs[4] = {0.f, 0.f, 0.f, 0.f};
    if (wk == 0) {
        const float* c0p = c0in + layer * BB * HH;
        cs[0] = c0p[r0 * HH + cb + j0];
        cs[1] = c0p[r0 * HH + cb + j0 + 1];
        cs[2] = c0p[(r0 + 8) * HH + cb + j0];
        cs[3] = c0p[(r0 + 8) * HH + cb + j0 + 1];
    }

    float bz0[4], bz1[4];
#pragma unroll
    for (int g = 0; g < 4; ++g) {
        bz0[g] = bs[g * 8 + j0];
        bz1[g] = bs[g * 8 + j0 + 1];
    }
    const float wl0 = wl[j0], wl1 = wl[j0 + 1];

    gbar();

#pragma unroll 1
    for (int s = 0; s <= TT; ++s) {
        const bool active = layer ? (s >= 1) : (s < TT);
        float acc[4][4];
        if (active) {
            if (wk == 0) {
#pragma unroll
                for (int g = 0; g < 4; ++g) {
                    acc[g][0] = bz0[g]; acc[g][1] = bz1[g];
                    acc[g][2] = bz0[g]; acc[g][3] = bz1[g];
                }
            } else {
#pragma unroll
                for (int g = 0; g < 4; ++g)
                    acc[g][0] = acc[g][1] = acc[g][2] = acc[g][3] = 0.0f;
            }
            if (layer == 0) {
                // pairs: wk0 = x(32) + h[0:48);  wk1 = h[48:128)
                const uint2* hprev = g_h0[(s + 1) & 1];
                if (wk == 0) {
                    gemm_span(acc, g_x2 + (size_t)s * ((II / 2) * BB), II / 2, 0,
                              Wsh, ldp, r0, lane);
                    gemm_span(acc, hprev, 48, II / 2, Wsh, ldp, r0, lane);
                } else {
                    gemm_span(acc, hprev + 48 * BB, 80, II / 2 + 48, Wsh, ldp, r0, lane);
                }
            } else {
                // pairs: wk0 = hs0 (128 pairs); wk1 = h1 (128 pairs)
                int t = s - 1;
                if (wk == 0) {
                    gemm_span(acc, g_h0[t & 1], 128, 0, Wsh, ldp, r0, lane);
                } else {
                    gemm_span(acc, g_h1[s & 1], 128, 128, Wsh, ldp, r0, lane);
                }
            }
            if (wk == 1) {
#pragma unroll
                for (int g = 0; g < 4; ++g)
                    red[g * 128 + wr * 32 + lane] =
                        make_float4(acc[g][0], acc[g][1], acc[g][2], acc[g][3]);
            }
        }
        __syncthreads();
        if (active && wk == 0) {
#pragma unroll
            for (int g = 0; g < 4; ++g) {
                float4 v = red[g * 128 + wr * 32 + lane];
                acc[g][0] += v.x; acc[g][1] += v.y;
                acc[g][2] += v.z; acc[g][3] += v.w;
            }
            float h[4];
#pragma unroll
            for (int e = 0; e < 4; ++e) {
                float ig = sigm(acc[0][e]);
                float fg = sigm(acc[1][e]);
                float gg = tanhx(acc[2][e]);
                float og = sigm(acc[3][e]);
                float c = fg * cs[e] + ig * gg;
                cs[e] = c;
                h[e] = og * tanhx(c);
            }
            uint2* hb2 = layer ? g_h1[(s - 1) & 1] : g_h0[s & 1];
            int pidx = (cb >> 1) + (lane & 3);
            hb2[pidx * BB + r0] = split_pair(h[0], h[1]);
            hb2[pidx * BB + r0 + 8] = split_pair(h[2], h[3]);
            if (layer == 1) {
                int t = s - 1;
                float p0 = h[0] * wl0 + h[1] * wl1;
                float p1 = h[2] * wl0 + h[3] * wl1;
                p0 += __shfl_xor_sync(0xffffffffu, p0, 1);
                p0 += __shfl_xor_sync(0xffffffffu, p0, 2);
                p1 += __shfl_xor_sync(0xffffffffu, p1, 1);
                p1 += __shfl_xor_sync(0xffffffffu, p1, 2);
                if ((lane & 3) == 0) {
                    atomicAdd(out + (size_t)t * BB + r0, p0);
                    atomicAdd(out + (size_t)t * BB + r0 + 8, p1);
                }
            }
        }
        gbar();
    }
}

extern "C" void kernel_launch(void* const* d_in, const int* in_sizes, int n_in,
                              void* d_out, int out_size) {
    (void)in_sizes; (void)n_in; (void)out_size;
    cudaFuncSetAttribute(lstm_kernel, cudaFuncAttributeMaxDynamicSharedMemorySize, SMEMB);
    lstm_kernel<<<NCTA, NTH, SMEMB>>>(
        (const float*)d_in[0], (const float*)d_in[1], (const float*)d_in[2],
        (const float*)d_in[3], (const float*)d_in[4], (const float*)d_in[5],
        (const float*)d_in[6], (const float*)d_in[7], (const float*)d_in[8],
        (const float*)d_in[9], (const float*)d_in[10], (const float*)d_in[11],
        (const float*)d_in[12], (float*)d_out);
}

// round 17
// speedup vs baseline: 2.6176x; 1.0630x over previous
#include <cuda_runtime.h>
#include <cuda_bf16.h>
#include <cstdint>

#define TT 2048
#define BB 128
#define HH 256
#define II 64
#define NCTA 128
#define NTH 256
#define K0 (II + HH)      // 320
#define K1 (HH + HH)      // 512
#define P0 (K0 / 2)       // 160 pairs
#define P1 (K1 / 2)       // 256 pairs
#define LDP0 (P0 + 8)     // 168
#define LDP1 (P1 + 8)     // 264
#define WSH_WORDS (32 * LDP1)
#define BS_OFF (WSH_WORDS * 8)
#define WL_OFF (BS_OFF + 32 * 4)
#define RED_OFF (WL_OFF + 64)
#define SMEMB (RED_OFF + 512 * 16)

// A operands: [pair][batch] uint2 = (bf16x2 hi-plane pair, bf16x2 lo-plane pair)
__device__ uint2 g_x2[(size_t)TT * (II / 2) * BB];
__device__ uint2 g_h0[2][(HH / 2) * BB];
__device__ uint2 g_h1[2][(HH / 2) * BB];
__device__ unsigned g_cnt;                 // init barrier only
__device__ unsigned g_gen;
__device__ unsigned g_step[2][2][32];      // [layer][bhalf][pad to 128B], slot 0 used

// --- one-shot full-grid init barrier (unchanged mechanism) ---
__device__ __forceinline__ void init_gbar() {
    __syncthreads();
    if (threadIdx.x == 0) {
        unsigned old = *((volatile unsigned*)&g_gen);
        __threadfence();
        if (atomicAdd(&g_cnt, 1u) == NCTA - 1) {
            atomicExch(&g_cnt, 0u);
            __threadfence();
            atomicAdd(&g_gen, 1u);
        } else {
            while (*((volatile unsigned*)&g_gen) == old) { }
        }
        __threadfence();
    }
    __syncthreads();
}

__device__ __forceinline__ unsigned ldacq(const unsigned* p) {
    unsigned v;
    asm volatile("ld.acquire.gpu.global.u32 %0, [%1];" : "=r"(v) : "l"(p) : "memory");
    return v;
}
__device__ __forceinline__ void arrive(unsigned* p) {
    asm volatile("fence.acq_rel.gpu;" ::: "memory");
    asm volatile("red.relaxed.gpu.global.add.u32 [%0], %1;" :: "l"(p), "r"(1u) : "memory");
}

// split a,b into bf16 hi/lo planes; low 16 bits = first element
__device__ __forceinline__ uint2 split_pair(float a, float b) {
    __nv_bfloat16 ah = __float2bfloat16(a);
    __nv_bfloat16 bh = __float2bfloat16(b);
    __nv_bfloat16 al = __float2bfloat16(a - __bfloat162float(ah));
    __nv_bfloat16 bl = __float2bfloat16(b - __bfloat162float(bh));
    unsigned hw = ((unsigned)__bfloat16_as_ushort(bh) << 16) | __bfloat16_as_ushort(ah);
    unsigned lw = ((unsigned)__bfloat16_as_ushort(bl) << 16) | __bfloat16_as_ushort(al);
    return make_uint2(hw, lw);
}

__device__ __forceinline__ void mma16(float (&c)[4], unsigned a0, unsigned a1,
                                      unsigned a2, unsigned a3, unsigned b0, unsigned b1) {
    asm volatile(
        "mma.sync.aligned.m16n8k16.row.col.f32.bf16.bf16.f32 "
        "{%0,%1,%2,%3},{%4,%5,%6,%7},{%8,%9},{%0,%1,%2,%3};"
        : "+f"(c[0]), "+f"(c[1]), "+f"(c[2]), "+f"(c[3])
        : "r"(a0), "r"(a1), "r"(a2), "r"(a3), "r"(b0), "r"(b1));
}

__device__ __forceinline__ float sigm(float x) { return 1.0f / (1.0f + __expf(-x)); }
__device__ __forceinline__ float tanhx(float x) { return 1.0f - 2.0f / (__expf(2.0f * x) + 1.0f); }

// A2: [npairs][BB] uint2 (hi word, lo word). poff = global pair offset into
// weights. Wsh slot-interleaved so uint4 at slot 2*kk = (hi_kk, lo_kk, hi_kk+4, lo_kk+4).
__device__ __forceinline__ void gemm_span(float (&acc)[4][4],
                                          const uint2* __restrict__ A2, int npairs, int poff,
                                          const uint2* __restrict__ Wsh, int ldp,
                                          int r0, int lane) {
    const int kk = lane & 3;
    const int gq = lane >> 2;
    const uint2* pA = A2 + kk * BB + r0;
    const uint2* wb = Wsh + gq * ldp + poff + 2 * kk;
#pragma unroll 4
    for (int p = 0; p < npairs; p += 8) {
        uint2 u0 = __ldcg(pA + p * BB);
        uint2 u1 = __ldcg(pA + p * BB + 8);
        uint2 u2 = __ldcg(pA + (p + 4) * BB);
        uint2 u3 = __ldcg(pA + (p + 4) * BB + 8);
        uint4 w4[4];
#pragma unroll
        for (int g = 0; g < 4; ++g)
            w4[g] = *reinterpret_cast<const uint4*>(wb + g * 8 * ldp + p);
#pragma unroll
        for (int g = 0; g < 4; ++g)   // hi*hi
            mma16(acc[g], u0.x, u1.x, u2.x, u3.x, w4[g].x, w4[g].z);
#pragma unroll
        for (int g = 0; g < 4; ++g)   // lo*hi
            mma16(acc[g], u0.y, u1.y, u2.y, u3.y, w4[g].x, w4[g].z);
#pragma unroll
        for (int g = 0; g < 4; ++g)   // hi*lo
            mma16(acc[g], u0.x, u1.x, u2.x, u3.x, w4[g].y, w4[g].w);
    }
}

__global__ void __launch_bounds__(NTH, 1)
lstm_kernel(const float* __restrict__ x, const float* __restrict__ h0in,
            const float* __restrict__ c0in,
            const float* __restrict__ Wih0, const float* __restrict__ Whh0,
            const float* __restrict__ bih0, const float* __restrict__ bhh0,
            const float* __restrict__ Wih1, const float* __restrict__ Whh1,
            const float* __restrict__ bih1, const float* __restrict__ bhh1,
            const float* __restrict__ Wlin, const float* __restrict__ blin,
            float* __restrict__ out) {
    extern __shared__ char sh[];
    uint2* Wsh = (uint2*)sh;
    float* bs = (float*)(sh + BS_OFF);
    float* wl = (float*)(sh + WL_OFF);
    float4* red = (float4*)(sh + RED_OFF);

    const int tid = threadIdx.x;
    const int cta = blockIdx.x;
    const int layer = cta >> 6;
    const int sub = cta & 63;
    const int cb = (sub >> 1) * 8;     // first hidden column (8 per CTA)
    const int bhalf = sub & 1;
    const int P = layer ? P1 : P0;
    const int ldp = layer ? LDP1 : LDP0;
    const int KX = layer ? HH : II;
    const float* Wih = layer ? Wih1 : Wih0;
    const float* Whh = layer ? Whh1 : Whh0;
    const float* bi = layer ? bih1 : bih0;
    const float* bh = layer ? bhh1 : bhh0;

    const unsigned* cntA = &g_step[0][bhalf][0];
    const unsigned* cntB = &g_step[1][bhalf][0];
    unsigned* cntOwn = &g_step[layer][bhalf][0];

    // init: reset counters, transpose+split x and initial h, out = b_lin
    if (cta == 0 && tid < 4) g_step[tid >> 1][tid & 1][0] = 0u;
    {
        int g = cta * NTH + tid, gs = NCTA * NTH;
        for (size_t i = g; i < (size_t)TT * BB * (II / 2); i += gs) {
            size_t t = i / (BB * (II / 2));
            int rem = (int)(i - t * (BB * (II / 2)));
            int r = rem / (II / 2), p = rem - r * (II / 2);
            const float* xp = x + t * (BB * II) + r * II + 2 * p;
            g_x2[t * ((II / 2) * BB) + p * BB + r] = split_pair(xp[0], xp[1]);
        }
        for (int i = g; i < BB * (HH / 2); i += gs) {
            int r = i / (HH / 2), p = i - r * (HH / 2);
            g_h0[1][p * BB + r] = split_pair(h0in[r * HH + 2 * p], h0in[r * HH + 2 * p + 1]);
            const float* hp = h0in + BB * HH + r * HH + 2 * p;
            g_h1[1][p * BB + r] = split_pair(hp[0], hp[1]);
        }
        float bl = blin[0];
        for (int i = g; i < TT * BB; i += gs) out[i] = bl;
    }

    // stage split weights: slot interleave (pair pp<4 -> slot 2pp; else 2(pp-4)+1)
    for (int i = tid; i < 32 * P; i += NTH) {
        int n = i / P, p = i - n * P;
        int row = (n >> 3) * HH + cb + (n & 7);
        int k0 = 2 * p, k1 = 2 * p + 1;
        float w0 = (k0 < KX) ? Wih[row * KX + k0] : Whh[row * HH + (k0 - KX)];
        float w1 = (k1 < KX) ? Wih[row * KX + k1] : Whh[row * HH + (k1 - KX)];
        int kc = p >> 3, pp = p & 7;
        int slot = kc * 8 + ((pp < 4) ? (2 * pp) : (2 * (pp - 4) + 1));
        Wsh[n * ldp + slot] = split_pair(w0, w1);
    }
    if (tid < 32) {
        int row = (tid >> 3) * HH + cb + (tid & 7);
        bs[tid] = bi[row] + bh[row];
    }
    if (tid < 8) wl[tid] = layer ? Wlin[cb + tid] : 0.0f;
    __syncthreads();

    const int w = tid >> 5;            // 8 warps
    const int wk = w & 1;              // K-half
    const int wr = w >> 1;             // row tile 0..3
    const int lane = tid & 31;
    const int r0 = 64 * bhalf + 16 * wr + (lane >> 2);  // rows r0, r0+8
    const int j0 = 2 * (lane & 3);

    float cs[4] = {0.f, 0.f, 0.f, 0.f};
    if (wk == 0) {
        const float* c0p = c0in + layer * BB * HH;
        cs[0] = c0p[r0 * HH + cb + j0];
        cs[1] = c0p[r0 * HH + cb + j0 + 1];
        cs[2] = c0p[(r0 + 8) * HH + cb + j0];
        cs[3] = c0p[(r0 + 8) * HH + cb + j0 + 1];
    }

    float bz0[4], bz1[4];
#pragma unroll
    for (int g = 0; g < 4; ++g) {
        bz0[g] = bs[g * 8 + j0];
        bz1[g] = bs[g * 8 + j0 + 1];
    }
    const float wl0 = wl[j0], wl1 = wl[j0 + 1];

    init_gbar();   // scratch + counters + weights visible everywhere

#pragma unroll 1
    for (int s = 0; s <= TT; ++s) {
        const bool active = layer ? (s >= 1) : (s < TT);
        // wait: group-local counters. A >= 32*s, B >= 32*(s-1).
        if (active && tid == 0) {
            unsigned tgtA = 32u * (unsigned)s;
            if (tgtA) while (ldacq(cntA) < tgtA) { }
            int tgtB = 32 * (s - 1);
            if (tgtB > 0) while ((int)ldacq(cntB) < tgtB) { }
        }
        __syncthreads();
        float acc[4][4];
        if (active) {
            if (wk == 0) {
#pragma unroll
                for (int g = 0; g < 4; ++g) {
                    acc[g][0] = bz0[g]; acc[g][1] = bz1[g];
                    acc[g][2] = bz0[g]; acc[g][3] = bz1[g];
                }
            } else {
#pragma unroll
                for (int g = 0; g < 4; ++g)
                    acc[g][0] = acc[g][1] = acc[g][2] = acc[g][3] = 0.0f;
            }
            if (layer == 0) {
                // pairs: wk0 = x(32) + h[0:48);  wk1 = h[48:128)
                const uint2* hprev = g_h0[(s + 1) & 1];
                if (wk == 0) {
                    gemm_span(acc, g_x2 + (size_t)s * ((II / 2) * BB), II / 2, 0,
                              Wsh, ldp, r0, lane);
                    gemm_span(acc, hprev, 48, II / 2, Wsh, ldp, r0, lane);
                } else {
                    gemm_span(acc, hprev + 48 * BB, 80, II / 2 + 48, Wsh, ldp, r0, lane);
                }
            } else {
                int t = s - 1;
                if (wk == 0) {
                    gemm_span(acc, g_h0[t & 1], 128, 0, Wsh, ldp, r0, lane);
                } else {
                    gemm_span(acc, g_h1[s & 1], 128, 128, Wsh, ldp, r0, lane);
                }
            }
            if (wk == 1) {
#pragma unroll
                for (int g = 0; g < 4; ++g)
                    red[g * 128 + wr * 32 + lane] =
                        make_float4(acc[g][0], acc[g][1], acc[g][2], acc[g][3]);
            }
        }
        __syncthreads();
        if (active && wk == 0) {
#pragma unroll
            for (int g = 0; g < 4; ++g) {
                float4 v = red[g * 128 + wr * 32 + lane];
                acc[g][0] += v.x; acc[g][1] += v.y;
                acc[g][2] += v.z; acc[g][3] += v.w;
            }
            float h[4];
#pragma unroll
            for (int e = 0; e < 4; ++e) {
                float ig = sigm(acc[0][e]);
                float fg = sigm(acc[1][e]);
                float gg = tanhx(acc[2][e]);
                float og = sigm(acc[3][e]);
                float c = fg * cs[e] + ig * gg;
                cs[e] = c;
                h[e] = og * tanhx(c);
            }
            uint2* hb2 = layer ? g_h1[(s - 1) & 1] : g_h0[s & 1];
            int pidx = (cb >> 1) + (lane & 3);
            hb2[pidx * BB + r0] = split_pair(h[0], h[1]);
            hb2[pidx * BB + r0 + 8] = split_pair(h[2], h[3]);
            if (layer == 1) {
                int t = s - 1;
                float p0 = h[0] * wl0 + h[1] * wl1;
                float p1 = h[2] * wl0 + h[3] * wl1;
                p0 += __shfl_xor_sync(0xffffffffu, p0, 1);
                p0 += __shfl_xor_sync(0xffffffffu, p0, 2);
                p1 += __shfl_xor_sync(0xffffffffu, p1, 1);
                p1 += __shfl_xor_sync(0xffffffffu, p1, 2);
                if ((lane & 3) == 0) {
                    atomicAdd(out + (size_t)t * BB + r0, p0);
                    atomicAdd(out + (size_t)t * BB + r0 + 8, p1);
                }
            }
        }
        __syncthreads();
        if (active && tid == 0) arrive(cntOwn);
    }
}

extern "C" void kernel_launch(void* const* d_in, const int* in_sizes, int n_in,
                              void* d_out, int out_size) {
    (void)in_sizes; (void)n_in; (void)out_size;
    cudaFuncSetAttribute(lstm_kernel, cudaFuncAttributeMaxDynamicSharedMemorySize, SMEMB);
    lstm_kernel<<<NCTA, NTH, SMEMB>>>(
        (const float*)d_in[0], (const float*)d_in[1], (const float*)d_in[2],
        (const float*)d_in[3], (const float*)d_in[4], (const float*)d_in[5],
        (const float*)d_in[6], (const float*)d_in[7], (const float*)d_in[8],
        (const float*)d_in[9], (const float*)d_in[10], (const float*)d_in[11],
        (const float*)d_in[12], (float*)d_out);
}